// round 1
// baseline (speedup 1.0000x reference)
#include <cuda_runtime.h>
#include <math.h>

#define N_ 2048
#define E_ 65536
#define D_ 512

#define MB_ 16      // MIS blocks
#define MT_ 128     // MIS threads per block (16*128 = 2048 = N_)

// ---------------- static device scratch (no allocations allowed) ----------------
__device__ int   g_degin[N_], g_degout[N_];
__device__ int   g_rpin[N_ + 1], g_rpout[N_ + 1];
__device__ int   g_curin[N_], g_curout[N_];
__device__ int   g_cscsrc[E_];        // CSC: senders grouped by receiver (col)
__device__ int   g_csrdst[E_];        // CSR: dst grouped by src (row)
__device__ float g_csrw[E_];          // prescaled 0.5*w/s_row
__device__ float g_s[N_], g_invs[N_], g_dd[N_], g_diag[N_];
__device__ int   g_a[N_], g_bb[N_], g_mis[N_], g_mka[N_], g_mkb[N_];
__device__ int   g_qlist[N_], g_colmap[N_];
__device__ int   g_M;
__device__ int   g_cluster[N_];
__device__ int   g_counts[N_];
__device__ int   g_cnt[2];
__device__ unsigned g_barcnt;
__device__ float g_B[(size_t)N_ * N_]; // compact rw[:, MIS] (stride = M)

__device__ __forceinline__ int ldvi(const int* p) { return *(const volatile int*)p; }

// ---------------- init (also resets barrier counter each replay) ----------------
__global__ void k_init()
{
    int i = blockIdx.x * blockDim.x + threadIdx.x;
    if (i < N_) { g_degin[i] = 0; g_degout[i] = 0; g_s[i] = 0.f; g_diag[i] = 0.f; g_counts[i] = 0; }
    if (i == 0) { g_cnt[0] = 0; g_cnt[1] = 0; g_barcnt = 0u; }
}

// ---------------- pass 1 over edges: degrees, row sums, diagonal ----------------
__global__ void k_edges1(const int* __restrict__ ei, const float* __restrict__ ea)
{
    int e = blockIdx.x * blockDim.x + threadIdx.x;
    if (e >= E_) return;
    int r = ei[e], c = ei[E_ + e];
    float w = ea[e];
    atomicAdd(&g_degin[c], 1);
    atomicAdd(&g_degout[r], 1);
    atomicAdd(&g_s[r], w);
    if (r == c) atomicAdd(&g_diag[r], w);
}

// ---------------- scans (CSR/CSC rowptr), inv rowsum, lazy-walk diag ----------------
__global__ void k_scan()
{
    __shared__ int sA[N_], sB[N_];
    int t = threadIdx.x;
    for (int pass = 0; pass < 2; pass++) {
        const int* src = pass ? g_degout : g_degin;
        int* rp  = pass ? g_rpout : g_rpin;
        int* cur = pass ? g_curout : g_curin;
        for (int i = t; i < N_; i += blockDim.x) sA[i] = src[i];
        __syncthreads();
        int* in = sA; int* out = sB;
        for (int off = 1; off < N_; off <<= 1) {
            for (int i = t; i < N_; i += blockDim.x)
                out[i] = in[i] + (i >= off ? in[i - off] : 0);
            __syncthreads();
            int* tmp = in; in = out; out = tmp;
        }
        for (int i = t; i < N_; i += blockDim.x) { rp[i + 1] = in[i]; cur[i] = i ? in[i - 1] : 0; }
        if (t == 0) rp[0] = 0;
        __syncthreads();
    }
    // rw = 0.5 * A_n + diag(d),  d_i = 0.5*(1 + A_n[ii]),  A_n = adj / max(s,1-style)
    for (int i = t; i < N_; i += blockDim.x) {
        float s = g_s[i];
        float inv = s > 0.f ? 1.f / s : 1.f;
        g_invs[i] = inv;
        g_dd[i] = 0.5f * (1.f + g_diag[i] * inv);
    }
}

// ---------------- pass 2: fill CSC/CSR (CSR weights prescaled) ----------------
__global__ void k_edges2(const int* __restrict__ ei, const float* __restrict__ ea)
{
    int e = blockIdx.x * blockDim.x + threadIdx.x;
    if (e >= E_) return;
    int r = ei[e], c = ei[E_ + e];
    int p = atomicAdd(&g_curin[c], 1);
    g_cscsrc[p] = r;
    int q = atomicAdd(&g_curout[r], 1);
    g_csrdst[q] = c;
    g_csrw[q] = 0.5f * ea[e] * g_invs[r];
}

// ---------------- software grid barrier (monotonic counter, reset in k_init) ----------------
__device__ __forceinline__ void gridbar(unsigned& phase)
{
    __syncthreads();
    if (threadIdx.x == 0) {
        __threadfence();
        unsigned tgt = (++phase) * (unsigned)MB_;
        atomicAdd(&g_barcnt, 1u);
        while (*((volatile unsigned*)&g_barcnt) < tgt) {}
        __threadfence();
    }
    __syncthreads();
}

// ---------------- k-hop MIS: persistent kernel, 1 thread per node ----------------
__global__ void k_mis(const int* __restrict__ rank)
{
    int tid = blockIdx.x * blockDim.x + threadIdx.x;
    int myrank = 0;
    if (tid < N_) { myrank = rank[tid]; g_a[tid] = myrank; g_mis[tid] = 0; }
    unsigned ph = 0;
    gridbar(ph);

    for (int iter = 0; iter < N_ + 2; iter++) {
        // ---- min-prop hop 1: a -> bb
        if (tid < N_) {
            int m = ldvi(&g_a[tid]);
            int beg = g_rpin[tid], end = g_rpin[tid + 1];
            for (int e = beg; e < end; e++) m = min(m, ldvi(&g_a[g_cscsrc[e]]));
            g_bb[tid] = m;
        }
        gridbar(ph);
        // ---- min-prop hop 2: bb -> a
        if (tid < N_) {
            int m = ldvi(&g_bb[tid]);
            int beg = g_rpin[tid], end = g_rpin[tid + 1];
            for (int e = beg; e < end; e++) m = min(m, ldvi(&g_bb[g_cscsrc[e]]));
            g_a[tid] = m;
        }
        gridbar(ph);
        // ---- mis |= (rank == mr); mk = mis
        if (tid < N_) {
            int mi = g_mis[tid] | ((myrank == ldvi(&g_a[tid])) ? 1 : 0);
            g_mis[tid] = mi;
            g_mka[tid] = mi;
        }
        gridbar(ph);
        // ---- or-prop hop 1: mka -> mkb
        if (tid < N_) {
            int m = ldvi(&g_mka[tid]);
            int beg = g_rpin[tid], end = g_rpin[tid + 1];
            for (int e = beg; e < end && m == 0; e++) m = max(m, ldvi(&g_mka[g_cscsrc[e]]));
            g_mkb[tid] = m;
        }
        gridbar(ph);
        // ---- or-prop hop 2: mkb -> mka
        if (tid < N_) {
            int m = ldvi(&g_mkb[tid]);
            int beg = g_rpin[tid], end = g_rpin[tid + 1];
            for (int e = beg; e < end && m == 0; e++) m = max(m, ldvi(&g_mkb[g_cscsrc[e]]));
            g_mka[tid] = m;
        }
        gridbar(ph);
        // ---- finalize: mask, mr reset, count unmasked
        if (tid == 0) g_cnt[(iter + 1) & 1] = 0;
        if (tid < N_) {
            int mask = ldvi(&g_mka[tid]) > 0;
            g_a[tid] = mask ? N_ : myrank;
            if (!mask) atomicAdd(&g_cnt[iter & 1], 1);
        }
        gridbar(ph);
        if (ldvi(&g_cnt[iter & 1]) == 0) break;
    }
}

// ---------------- compact MIS columns (ascending node index) ----------------
__global__ void k_compact()
{
    __shared__ int sA[N_], sB[N_];
    int t = threadIdx.x;
    for (int i = t; i < N_; i += blockDim.x) sA[i] = g_mis[i];
    __syncthreads();
    int* in = sA; int* out = sB;
    for (int off = 1; off < N_; off <<= 1) {
        for (int i = t; i < N_; i += blockDim.x)
            out[i] = in[i] + (i >= off ? in[i - off] : 0);
        __syncthreads();
        int* tmp = in; in = out; out = tmp;
    }
    for (int i = t; i < N_; i += blockDim.x) {
        if (g_mis[i]) { int p = in[i] - 1; g_colmap[i] = p; g_qlist[p] = i; }
        else g_colmap[i] = -1;
    }
    if (t == 0) g_M = in[N_ - 1];
}

// ---------------- B = rw[:, MIS]  (compact, stride M) ----------------
__global__ void k_zeroB()
{
    int M = g_M;
    size_t tot = (size_t)N_ * (size_t)M;
    for (size_t idx = blockIdx.x * (size_t)blockDim.x + threadIdx.x; idx < tot;
         idx += (size_t)gridDim.x * blockDim.x)
        g_B[idx] = 0.f;
}

__global__ void k_buildB(const int* __restrict__ ei, const float* __restrict__ ea)
{
    int e = blockIdx.x * blockDim.x + threadIdx.x;
    if (e >= E_) return;
    int r = ei[e], c = ei[E_ + e];
    int cm = g_colmap[c];
    if (cm >= 0) atomicAdd(&g_B[(size_t)r * g_M + cm], 0.5f * ea[e] * g_invs[r]);
}

__global__ void k_diagB()
{
    int i = blockIdx.x * blockDim.x + threadIdx.x;
    if (i < N_ && g_mis[i]) g_B[(size_t)i * g_M + g_colmap[i]] += g_dd[i];
}

// ---------------- c = rw @ B (sparse row), fused Gumbel-argmax -> cluster ----------------
__global__ void k_spmm(const float* __restrict__ u)
{
    int i = blockIdx.x;
    int t = threadIdx.x;
    int M = g_M;
    int nk = (M + 127) >> 7;   // <= 16
    float acc[16];
#pragma unroll
    for (int k = 0; k < 16; k++) acc[k] = 0.f;

    int beg = g_rpout[i], end = g_rpout[i + 1];
    for (int e = beg; e < end; e++) {
        int j = g_csrdst[e]; float wn = g_csrw[e];
        const float* Bj = g_B + (size_t)j * M;
        for (int k = 0; k < nk; k++) { int m = t + (k << 7); if (m < M) acc[k] += wn * Bj[m]; }
    }
    {
        float dd = g_dd[i];
        const float* Bi = g_B + (size_t)i * M;
        for (int k = 0; k < nk; k++) { int m = t + (k << 7); if (m < M) acc[k] += dd * Bi[m]; }
    }

    // argmax of log(c)+gumbel over MIS columns; row-normalization is a per-row
    // positive scale of c and cannot change the argmax -> skipped.
    float best = -INFINITY; int bq = 0x7FFFFFFF;
    const float* ui = u + (size_t)i * N_;
    for (int k = 0; k < nk; k++) {
        int m = t + (k << 7);
        if (m < M) {
            float cv = acc[k];
            if (cv > 0.f) {
                int q = g_qlist[m];
                float uu = ui[q];
                float gum = -logf(-logf(uu + 1e-20f) + 1e-20f);
                float lg = logf(fmaxf(cv, 1e-30f)) + gum;
                if (lg > best || (lg == best && q < bq)) { best = lg; bq = q; }
            }
        }
    }
    __shared__ float sv[128]; __shared__ int sq[128];
    sv[t] = best; sq[t] = bq;
    __syncthreads();
    for (int o = 64; o > 0; o >>= 1) {
        if (t < o) {
            float v = sv[t + o]; int q = sq[t + o];
            if (v > sv[t] || (v == sv[t] && q < sq[t])) { sv[t] = v; sq[t] = q; }
        }
        __syncthreads();
    }
    if (t == 0) g_cluster[i] = (sq[0] == 0x7FFFFFFF) ? 0 : sq[0];   // all -inf -> argmax = 0
}

__global__ void k_counts()
{
    int i = blockIdx.x * blockDim.x + threadIdx.x;
    if (i < N_) atomicAdd(&g_counts[g_cluster[i]], 1);
}

// ---------------- outputs ----------------
__global__ void k_fillzero(float4* __restrict__ o, size_t tot4)
{
    for (size_t idx = blockIdx.x * (size_t)blockDim.x + threadIdx.x; idx < tot4;
         idx += (size_t)gridDim.x * blockDim.x)
        o[idx] = make_float4(0.f, 0.f, 0.f, 0.f);
}

__global__ void k_misout(float* __restrict__ o)
{
    int i = blockIdx.x * blockDim.x + threadIdx.x;
    if (i < N_) o[i] = g_mis[i] ? 1.f : 0.f;
}

__global__ void k_scatter(float* __restrict__ chard, float* __restrict__ pinv)
{
    int i = blockIdx.x * blockDim.x + threadIdx.x;
    if (i < N_) {
        int c = g_cluster[i];
        chard[(size_t)i * N_ + c] = 1.f;
        pinv[(size_t)c * N_ + i] = 1.f / (float)g_counts[c];
    }
}

__global__ void k_adjc(const int* __restrict__ ei, const float* __restrict__ ea,
                       float* __restrict__ adjc)
{
    int e = blockIdx.x * blockDim.x + threadIdx.x;
    if (e >= E_) return;
    int r = ei[e], c = ei[E_ + e];
    atomicAdd(&adjc[(size_t)g_cluster[r] * N_ + g_cluster[c]], ea[e]);
}

__global__ void k_xacc(const float* __restrict__ x, float* __restrict__ xp)
{
    int idx = blockIdx.x * blockDim.x + threadIdx.x;
    if (idx < N_ * D_) {
        int i = idx / D_, d = idx % D_;
        atomicAdd(&xp[(size_t)g_cluster[i] * D_ + d], x[idx]);
    }
}

__global__ void k_xscale(float* __restrict__ xp)
{
    int idx = blockIdx.x * blockDim.x + threadIdx.x;
    if (idx < N_ * D_) {
        int a = idx / D_;
        int c = g_counts[a];
        if (c > 0) xp[idx] *= 1.f / (float)c;
    }
}

// ---------------- launch ----------------
extern "C" void kernel_launch(void* const* d_in, const int* in_sizes, int n_in,
                              void* d_out, int out_size)
{
    const int*   ei   = (const int*)d_in[0];     // edge_index [2, E]
    const float* ea   = (const float*)d_in[1];   // edge_attr  [E]
    const float* x    = (const float*)d_in[2];   // x          [N, D]
    const int*   rank = (const int*)d_in[3];     // rank       [N]
    const float* u    = (const float*)d_in[4];   // u          [N, N]

    float* out   = (float*)d_out;
    size_t nn    = (size_t)N_ * N_;
    float* adjc  = out;
    float* chard = out + nn;
    float* pinv  = out + 2 * nn;
    float* miso  = out + 3 * nn;
    float* xpool = out + 3 * nn + N_;

    (void)in_sizes; (void)n_in;

    k_init   <<<(N_ + 255) / 256, 256>>>();
    k_edges1 <<<(E_ + 255) / 256, 256>>>(ei, ea);
    k_scan   <<<1, 1024>>>();
    k_edges2 <<<(E_ + 255) / 256, 256>>>(ei, ea);
    k_mis    <<<MB_, MT_>>>(rank);
    k_compact<<<1, 1024>>>();
    k_zeroB  <<<1024, 256>>>();
    k_buildB <<<(E_ + 255) / 256, 256>>>(ei, ea);
    k_diagB  <<<(N_ + 255) / 256, 256>>>();
    k_spmm   <<<N_, 128>>>(u);
    k_counts <<<(N_ + 255) / 256, 256>>>();

    size_t tot4 = (size_t)out_size >> 2;   // out_size divisible by 4 here
    k_fillzero<<<4096, 256>>>((float4*)out, tot4);
    k_misout <<<(N_ + 255) / 256, 256>>>(miso);
    k_scatter<<<(N_ + 255) / 256, 256>>>(chard, pinv);
    k_adjc   <<<(E_ + 255) / 256, 256>>>(ei, ea, adjc);
    k_xacc   <<<(N_ * D_ + 255) / 256, 256>>>(x, xpool);
    k_xscale <<<(N_ * D_ + 255) / 256, 256>>>(xpool);
}

// round 2
// speedup vs baseline: 1.5758x; 1.5758x over previous
#include <cuda_runtime.h>
#include <math.h>

#define N_ 2048
#define E_ 65536
#define D_ 512

#define MB_ 32      // MIS blocks (all co-resident: 32 << 148 SMs)
#define MT_ 512     // MIS threads/block -> 512 warps total, 4 nodes/warp
#define NPW_ (N_ / (MB_ * MT_ / 32))   // nodes per warp = 4

// ---------------- static device scratch (no allocations allowed) ----------------
__device__ int   g_degin[N_], g_degout[N_];
__device__ int   g_rpin[N_ + 1], g_rpout[N_ + 1];
__device__ int   g_curin[N_], g_curout[N_];
__device__ int   g_cscsrc[E_];        // CSC: senders grouped by receiver (col)
__device__ int   g_csrdst[E_];        // CSR: dst grouped by src (row)
__device__ float g_csrw[E_];          // prescaled 0.5*w/s_row
__device__ float g_s[N_], g_invs[N_], g_dd[N_], g_diag[N_];
__device__ int   g_bb[N_], g_mis[N_], g_mka[N_], g_mkb[N_], g_a[N_];
__device__ int   g_qlist[N_], g_colmap[N_];
__device__ int   g_M;
__device__ int   g_cluster[N_];
__device__ int   g_counts[N_];
__device__ int   g_cnt[2];
__device__ unsigned g_barcnt;
__device__ float g_B[(size_t)N_ * N_]; // compact rw[:, MIS] (stride = M)

__device__ __forceinline__ int ldvi(const int* p) { return *(const volatile int*)p; }

// ---------------- init (also resets barrier counter each replay) ----------------
__global__ void k_init()
{
    int i = blockIdx.x * blockDim.x + threadIdx.x;
    if (i < N_) { g_degin[i] = 0; g_degout[i] = 0; g_s[i] = 0.f; g_diag[i] = 0.f; g_counts[i] = 0; }
    if (i == 0) { g_cnt[0] = 0; g_cnt[1] = 0; g_barcnt = 0u; }
}

// ---------------- pass 1 over edges: degrees, row sums, diagonal ----------------
__global__ void k_edges1(const int* __restrict__ ei, const float* __restrict__ ea)
{
    int e = blockIdx.x * blockDim.x + threadIdx.x;
    if (e >= E_) return;
    int r = ei[e], c = ei[E_ + e];
    float w = ea[e];
    atomicAdd(&g_degin[c], 1);
    atomicAdd(&g_degout[r], 1);
    atomicAdd(&g_s[r], w);
    if (r == c) atomicAdd(&g_diag[r], w);
}

// ---------------- scans (CSR/CSC rowptr), inv rowsum, lazy-walk diag ----------------
__global__ void k_scan()
{
    __shared__ int sA[N_], sB[N_];
    int t = threadIdx.x;
    for (int pass = 0; pass < 2; pass++) {
        const int* src = pass ? g_degout : g_degin;
        int* rp  = pass ? g_rpout : g_rpin;
        int* cur = pass ? g_curout : g_curin;
        for (int i = t; i < N_; i += blockDim.x) sA[i] = src[i];
        __syncthreads();
        int* in = sA; int* out = sB;
        for (int off = 1; off < N_; off <<= 1) {
            for (int i = t; i < N_; i += blockDim.x)
                out[i] = in[i] + (i >= off ? in[i - off] : 0);
            __syncthreads();
            int* tmp = in; in = out; out = tmp;
        }
        for (int i = t; i < N_; i += blockDim.x) { rp[i + 1] = in[i]; cur[i] = i ? in[i - 1] : 0; }
        if (t == 0) rp[0] = 0;
        __syncthreads();
    }
    for (int i = t; i < N_; i += blockDim.x) {
        float s = g_s[i];
        float inv = s > 0.f ? 1.f / s : 1.f;
        g_invs[i] = inv;
        g_dd[i] = 0.5f * (1.f + g_diag[i] * inv);   // lazy-walk diagonal
    }
}

// ---------------- pass 2: fill CSC/CSR (CSR weights prescaled) ----------------
__global__ void k_edges2(const int* __restrict__ ei, const float* __restrict__ ea)
{
    int e = blockIdx.x * blockDim.x + threadIdx.x;
    if (e >= E_) return;
    int r = ei[e], c = ei[E_ + e];
    int p = atomicAdd(&g_curin[c], 1);
    g_cscsrc[p] = r;
    int q = atomicAdd(&g_curout[r], 1);
    g_csrdst[q] = c;
    g_csrw[q] = 0.5f * ea[e] * g_invs[r];
}

// ---------------- software grid barrier (monotonic counter, reset in k_init) ----------------
__device__ __forceinline__ void gridbar(unsigned& phase)
{
    __syncthreads();
    if (threadIdx.x == 0) {
        __threadfence();
        unsigned tgt = (++phase) * (unsigned)MB_;
        atomicAdd(&g_barcnt, 1u);
        while (*((volatile unsigned*)&g_barcnt) < tgt) {}
        __threadfence();
    }
    __syncthreads();
}

// ---------------- k-hop MIS: persistent, warp-per-node, 4 barriers/iter ----------------
__global__ void k_mis(const int* __restrict__ rank)
{
    const int tid  = blockIdx.x * blockDim.x + threadIdx.x;
    const int wid  = tid >> 5;
    const int lane = tid & 31;
    const int n0   = wid * NPW_;

    for (int i = tid; i < N_; i += MB_ * MT_) { g_a[i] = rank[i]; g_mis[i] = 0; }
    unsigned ph = 0;
    gridbar(ph);

    for (int iter = 0; iter < N_; iter++) {
        // ---- min-prop hop 1: g_a -> g_bb
        for (int k = 0; k < NPW_; k++) {
            int n = n0 + k;
            int beg = g_rpin[n], end = g_rpin[n + 1];
            int m = ldvi(&g_a[n]);
            for (int e = beg + lane; e < end; e += 32) m = min(m, ldvi(&g_a[g_cscsrc[e]]));
            m = __reduce_min_sync(0xffffffffu, m);
            if (lane == 0) g_bb[n] = m;
        }
        gridbar(ph);
        // ---- min-prop hop 2 + mis update (2-hop min consumed locally)
        for (int k = 0; k < NPW_; k++) {
            int n = n0 + k;
            int beg = g_rpin[n], end = g_rpin[n + 1];
            int m = ldvi(&g_bb[n]);
            for (int e = beg + lane; e < end; e += 32) m = min(m, ldvi(&g_bb[g_cscsrc[e]]));
            m = __reduce_min_sync(0xffffffffu, m);
            if (lane == 0) {
                int mi = g_mis[n] | (rank[n] == m ? 1 : 0);
                g_mis[n] = mi;
                g_mka[n] = mi;
            }
        }
        gridbar(ph);
        // ---- or-prop hop 1: g_mka -> g_mkb
        for (int k = 0; k < NPW_; k++) {
            int n = n0 + k;
            int beg = g_rpin[n], end = g_rpin[n + 1];
            int m = ldvi(&g_mka[n]);
            for (int e = beg + lane; e < end; e += 32) m = max(m, ldvi(&g_mka[g_cscsrc[e]]));
            m = __reduce_max_sync(0xffffffffu, m);
            if (lane == 0) g_mkb[n] = m;
        }
        gridbar(ph);
        // ---- or-prop hop 2 + finalize (mask consumed locally)
        if (tid == 0) g_cnt[(iter + 1) & 1] = 0;
        for (int k = 0; k < NPW_; k++) {
            int n = n0 + k;
            int beg = g_rpin[n], end = g_rpin[n + 1];
            int m = ldvi(&g_mkb[n]);
            for (int e = beg + lane; e < end; e += 32) m = max(m, ldvi(&g_mkb[g_cscsrc[e]]));
            m = __reduce_max_sync(0xffffffffu, m);
            if (lane == 0) {
                int mask = m > 0;
                g_a[n] = mask ? N_ : rank[n];
                if (!mask) atomicAdd(&g_cnt[iter & 1], 1);
            }
        }
        gridbar(ph);
        if (ldvi(&g_cnt[iter & 1]) == 0) break;
    }

    // ---- fused compact: block 0 scans g_mis -> colmap/qlist/M ----
    if (blockIdx.x == 0) {
        __shared__ int sA[N_], sB[N_];
        int t = threadIdx.x;
        for (int i = t; i < N_; i += MT_) sA[i] = ldvi(&g_mis[i]);
        __syncthreads();
        int* in = sA; int* out = sB;
        for (int off = 1; off < N_; off <<= 1) {
            for (int i = t; i < N_; i += MT_)
                out[i] = in[i] + (i >= off ? in[i - off] : 0);
            __syncthreads();
            int* tmp = in; in = out; out = tmp;
        }
        for (int i = t; i < N_; i += MT_) {
            if (ldvi(&g_mis[i])) { int p = in[i] - 1; g_colmap[i] = p; g_qlist[p] = i; }
            else g_colmap[i] = -1;
        }
        if (t == 0) g_M = in[N_ - 1];
    }
}

// ---------------- B = rw[:, MIS] (compact, stride M) ----------------
__global__ void k_zeroB()
{
    int M = g_M;
    size_t tot = (size_t)N_ * (size_t)M;
    for (size_t idx = blockIdx.x * (size_t)blockDim.x + threadIdx.x; idx < tot;
         idx += (size_t)gridDim.x * blockDim.x)
        g_B[idx] = 0.f;
}

__global__ void k_buildB(const int* __restrict__ ei, const float* __restrict__ ea)
{
    int t = blockIdx.x * blockDim.x + threadIdx.x;
    if (t < E_) {
        int r = ei[t], c = ei[E_ + t];
        int cm = g_colmap[c];
        if (cm >= 0) atomicAdd(&g_B[(size_t)r * g_M + cm], 0.5f * ea[t] * g_invs[r]);
    } else {
        int i = t - E_;
        if (i < N_ && g_mis[i])
            atomicAdd(&g_B[(size_t)i * g_M + g_colmap[i]], g_dd[i]);
    }
}

// ---------------- c = rw @ B (sparse row), fused Gumbel-argmax + counts ----------------
__global__ void k_spmm(const float* __restrict__ u)
{
    int i = blockIdx.x;
    int t = threadIdx.x;
    int M = g_M;
    int nk = (M + 127) >> 7;   // <= 16
    float acc[16];
#pragma unroll
    for (int k = 0; k < 16; k++) acc[k] = 0.f;

    int beg = g_rpout[i], end = g_rpout[i + 1];
    for (int e = beg; e < end; e++) {
        int j = g_csrdst[e]; float wn = g_csrw[e];
        const float* Bj = g_B + (size_t)j * M;
        for (int k = 0; k < nk; k++) { int m = t + (k << 7); if (m < M) acc[k] += wn * Bj[m]; }
    }
    {
        float dd = g_dd[i];
        const float* Bi = g_B + (size_t)i * M;
        for (int k = 0; k < nk; k++) { int m = t + (k << 7); if (m < M) acc[k] += dd * Bi[m]; }
    }

    // argmax of log(c)+gumbel; row-normalization is a positive per-row scale -> skipped
    float best = -INFINITY; int bq = 0x7FFFFFFF;
    const float* ui = u + (size_t)i * N_;
    for (int k = 0; k < nk; k++) {
        int m = t + (k << 7);
        if (m < M) {
            float cv = acc[k];
            if (cv > 0.f) {
                int q = g_qlist[m];
                float uu = ui[q];
                float gum = -logf(-logf(uu + 1e-20f) + 1e-20f);
                float lg = logf(fmaxf(cv, 1e-30f)) + gum;
                if (lg > best || (lg == best && q < bq)) { best = lg; bq = q; }
            }
        }
    }
    __shared__ float sv[128]; __shared__ int sq[128];
    sv[t] = best; sq[t] = bq;
    __syncthreads();
    for (int o = 64; o > 0; o >>= 1) {
        if (t < o) {
            float v = sv[t + o]; int q = sq[t + o];
            if (v > sv[t] || (v == sv[t] && q < sq[t])) { sv[t] = v; sq[t] = q; }
        }
        __syncthreads();
    }
    if (t == 0) {
        int cl = (sq[0] == 0x7FFFFFFF) ? 0 : sq[0];
        g_cluster[i] = cl;
        atomicAdd(&g_counts[cl], 1);
    }
}

// ---------------- outputs ----------------
__global__ void k_fillzero(float4* __restrict__ o, size_t tot4)
{
    for (size_t idx = blockIdx.x * (size_t)blockDim.x + threadIdx.x; idx < tot4;
         idx += (size_t)gridDim.x * blockDim.x)
        o[idx] = make_float4(0.f, 0.f, 0.f, 0.f);
}

__global__ void k_outputs(float* __restrict__ miso, float* __restrict__ chard,
                          float* __restrict__ pinv)
{
    int i = blockIdx.x * blockDim.x + threadIdx.x;
    if (i < N_) {
        miso[i] = g_mis[i] ? 1.f : 0.f;
        int c = g_cluster[i];
        chard[(size_t)i * N_ + c] = 1.f;
        pinv[(size_t)c * N_ + i] = 1.f / (float)g_counts[c];
    }
}

__global__ void k_adjc(const int* __restrict__ ei, const float* __restrict__ ea,
                       float* __restrict__ adjc)
{
    int e = blockIdx.x * blockDim.x + threadIdx.x;
    if (e >= E_) return;
    int r = ei[e], c = ei[E_ + e];
    atomicAdd(&adjc[(size_t)g_cluster[r] * N_ + g_cluster[c]], ea[e]);
}

__global__ void k_xacc(const float* __restrict__ x, float* __restrict__ xp)
{
    int idx = blockIdx.x * blockDim.x + threadIdx.x;
    if (idx < N_ * D_) {
        int i = idx / D_, d = idx % D_;
        int c = g_cluster[i];
        float invc = 1.f / (float)g_counts[c];
        atomicAdd(&xp[(size_t)c * D_ + d], x[idx] * invc);
    }
}

// ---------------- launch ----------------
extern "C" void kernel_launch(void* const* d_in, const int* in_sizes, int n_in,
                              void* d_out, int out_size)
{
    const int*   ei   = (const int*)d_in[0];     // edge_index [2, E]
    const float* ea   = (const float*)d_in[1];   // edge_attr  [E]
    const float* x    = (const float*)d_in[2];   // x          [N, D]
    const int*   rank = (const int*)d_in[3];     // rank       [N]
    const float* u    = (const float*)d_in[4];   // u          [N, N]

    float* out   = (float*)d_out;
    size_t nn    = (size_t)N_ * N_;
    float* adjc  = out;
    float* chard = out + nn;
    float* pinv  = out + 2 * nn;
    float* miso  = out + 3 * nn;
    float* xpool = out + 3 * nn + N_;

    (void)in_sizes; (void)n_in;

    k_init    <<<(N_ + 255) / 256, 256>>>();
    k_edges1  <<<(E_ + 255) / 256, 256>>>(ei, ea);
    k_scan    <<<1, 1024>>>();
    k_edges2  <<<(E_ + 255) / 256, 256>>>(ei, ea);
    k_mis     <<<MB_, MT_>>>(rank);
    k_zeroB   <<<1024, 256>>>();
    k_buildB  <<<(E_ + N_ + 255) / 256, 256>>>(ei, ea);

    size_t tot4 = (size_t)out_size >> 2;   // out_size divisible by 4 here
    k_fillzero<<<4096, 256>>>((float4*)out, tot4);

    k_spmm    <<<N_, 128>>>(u);
    k_outputs <<<(N_ + 255) / 256, 256>>>(miso, chard, pinv);
    k_adjc    <<<(E_ + 255) / 256, 256>>>(ei, ea, adjc);
    k_xacc    <<<(N_ * D_ + 255) / 256, 256>>>(x, xpool);
}

// round 3
// speedup vs baseline: 2.1064x; 1.3367x over previous
#include <cuda_runtime.h>
#include <math.h>

#define N_ 2048
#define E_ 65536
#define D_ 512

#define MB_ 128     // MIS blocks (1/SM, all co-resident on 148-SM chip)
#define MT_ 512     // threads/block -> 2048 warps total = 1 warp per node

// ---------------- static device scratch (no allocations allowed) ----------------
__device__ int   g_degin[N_], g_degout[N_];
__device__ int   g_rpin[N_ + 1], g_rpout[N_ + 1];
__device__ int   g_curin[N_], g_curout[N_];
__device__ int   g_cscsrc[E_];        // CSC: senders grouped by receiver (col)
__device__ int   g_csrdst[E_];        // CSR: dst grouped by src (row)
__device__ float g_csrw[E_];          // prescaled 0.5*w/s_row
__device__ float g_s[N_], g_invs[N_], g_dd[N_], g_diag[N_];
__device__ int   g_bb[N_], g_mis[N_], g_mka[N_], g_mkb[N_], g_a[N_];
__device__ int   g_qlist[N_], g_colmap[N_];
__device__ int   g_M;
__device__ int   g_cluster[N_];
__device__ int   g_counts[N_];
__device__ int   g_cnt[2];
__device__ unsigned g_barcnt;
__device__ float g_B[(size_t)N_ * N_]; // compact rw[:, MIS] (stride = M)

__device__ __forceinline__ int ldvi(const int* p) { return *(const volatile int*)p; }

// ---------------- init (also resets barrier counter each replay) ----------------
__global__ void k_init()
{
    int i = blockIdx.x * blockDim.x + threadIdx.x;
    if (i < N_) { g_degin[i] = 0; g_degout[i] = 0; g_s[i] = 0.f; g_diag[i] = 0.f; g_counts[i] = 0; }
    if (i == 0) { g_cnt[0] = 0; g_cnt[1] = 0; g_barcnt = 0u; }
}

// ---------------- pass 1 over edges: degrees, row sums, diagonal ----------------
__global__ void k_edges1(const int* __restrict__ ei, const float* __restrict__ ea)
{
    int e = blockIdx.x * blockDim.x + threadIdx.x;
    if (e >= E_) return;
    int r = ei[e], c = ei[E_ + e];
    float w = ea[e];
    atomicAdd(&g_degin[c], 1);
    atomicAdd(&g_degout[r], 1);
    atomicAdd(&g_s[r], w);
    if (r == c) atomicAdd(&g_diag[r], w);
}

// ---------------- scans (CSR/CSC rowptr), inv rowsum, lazy-walk diag ----------------
__global__ void k_scan()
{
    __shared__ int sA[N_], sB[N_];
    int t = threadIdx.x;
    for (int pass = 0; pass < 2; pass++) {
        const int* src = pass ? g_degout : g_degin;
        int* rp  = pass ? g_rpout : g_rpin;
        int* cur = pass ? g_curout : g_curin;
        for (int i = t; i < N_; i += blockDim.x) sA[i] = src[i];
        __syncthreads();
        int* in = sA; int* out = sB;
        for (int off = 1; off < N_; off <<= 1) {
            for (int i = t; i < N_; i += blockDim.x)
                out[i] = in[i] + (i >= off ? in[i - off] : 0);
            __syncthreads();
            int* tmp = in; in = out; out = tmp;
        }
        for (int i = t; i < N_; i += blockDim.x) { rp[i + 1] = in[i]; cur[i] = i ? in[i - 1] : 0; }
        if (t == 0) rp[0] = 0;
        __syncthreads();
    }
    for (int i = t; i < N_; i += blockDim.x) {
        float s = g_s[i];
        float inv = s > 0.f ? 1.f / s : 1.f;
        g_invs[i] = inv;
        g_dd[i] = 0.5f * (1.f + g_diag[i] * inv);   // lazy-walk diagonal
    }
}

// ---------------- pass 2: fill CSC/CSR (CSR weights prescaled) ----------------
__global__ void k_edges2(const int* __restrict__ ei, const float* __restrict__ ea)
{
    int e = blockIdx.x * blockDim.x + threadIdx.x;
    if (e >= E_) return;
    int r = ei[e], c = ei[E_ + e];
    int p = atomicAdd(&g_curin[c], 1);
    g_cscsrc[p] = r;
    int q = atomicAdd(&g_curout[r], 1);
    g_csrdst[q] = c;
    g_csrw[q] = 0.5f * ea[e] * g_invs[r];
}

// ---------------- software grid barrier (monotonic counter, reset in k_init) ----------------
__device__ __forceinline__ void gridbar(unsigned& phase)
{
    __syncthreads();
    if (threadIdx.x == 0) {
        __threadfence();
        unsigned tgt = (++phase) * (unsigned)MB_;
        atomicAdd(&g_barcnt, 1u);
        while (*((volatile unsigned*)&g_barcnt) < tgt) {}
        __threadfence();
    }
    __syncthreads();
}

// ---------------- k-hop MIS: persistent, 1 warp/node, reg-cached CSC ----------------
__global__ void __launch_bounds__(MT_, 1) k_mis(const int* __restrict__ rank)
{
    const int tid  = blockIdx.x * blockDim.x + threadIdx.x;
    const int n    = tid >> 5;        // warp id == node id (2048 warps)
    const int lane = tid & 31;

    // init mr = rank, mis = 0
    for (int i = tid; i < N_; i += MB_ * MT_) { g_a[i] = rank[i]; g_mis[i] = 0; }

    // register-cache this node's in-edge sources (first 32; remainder looped)
    const int beg = g_rpin[n];
    const int end = g_rpin[n + 1];
    const int deg = end - beg;
    const int src = (lane < deg) ? g_cscsrc[beg + lane] : -1;
    const int rk  = rank[n];

    unsigned ph = 0;
    gridbar(ph);

    for (int iter = 0; iter < N_; iter++) {
        // ---- min-prop hop 1: g_a -> g_bb
        {
            int m = ldvi(&g_a[n]);
            if (src >= 0) m = min(m, ldvi(&g_a[src]));
            for (int e = beg + 32 + lane; e < end; e += 32) m = min(m, ldvi(&g_a[g_cscsrc[e]]));
            m = __reduce_min_sync(0xffffffffu, m);
            if (lane == 0) g_bb[n] = m;
        }
        gridbar(ph);
        // ---- min-prop hop 2 + mis update (consumed locally)
        {
            int m = ldvi(&g_bb[n]);
            if (src >= 0) m = min(m, ldvi(&g_bb[src]));
            for (int e = beg + 32 + lane; e < end; e += 32) m = min(m, ldvi(&g_bb[g_cscsrc[e]]));
            m = __reduce_min_sync(0xffffffffu, m);
            if (lane == 0) {
                int mi = g_mis[n] | (rk == m ? 1 : 0);
                g_mis[n] = mi;
                g_mka[n] = mi;
            }
        }
        gridbar(ph);
        // ---- or-prop hop 1: g_mka -> g_mkb
        {
            int m = ldvi(&g_mka[n]);
            if (src >= 0) m = max(m, ldvi(&g_mka[src]));
            for (int e = beg + 32 + lane; e < end; e += 32) m = max(m, ldvi(&g_mka[g_cscsrc[e]]));
            m = __reduce_max_sync(0xffffffffu, m);
            if (lane == 0) g_mkb[n] = m;
        }
        gridbar(ph);
        // ---- or-prop hop 2 + finalize (mask consumed locally)
        if (tid == 0) g_cnt[(iter + 1) & 1] = 0;
        {
            int m = ldvi(&g_mkb[n]);
            if (src >= 0) m = max(m, ldvi(&g_mkb[src]));
            for (int e = beg + 32 + lane; e < end; e += 32) m = max(m, ldvi(&g_mkb[g_cscsrc[e]]));
            m = __reduce_max_sync(0xffffffffu, m);
            if (lane == 0) {
                int mask = m > 0;
                g_a[n] = mask ? N_ : rk;
                if (!mask) atomicAdd(&g_cnt[iter & 1], 1);
            }
        }
        gridbar(ph);
        if (ldvi(&g_cnt[iter & 1]) == 0) break;
    }

    // ---- fused compact: block 0 scans g_mis -> colmap/qlist/M ----
    __shared__ int sA[N_], sB[N_];
    if (blockIdx.x == 0) {
        int t = threadIdx.x;
        for (int i = t; i < N_; i += MT_) sA[i] = ldvi(&g_mis[i]);
        __syncthreads();
        int* in = sA; int* out = sB;
        for (int off = 1; off < N_; off <<= 1) {
            for (int i = t; i < N_; i += MT_)
                out[i] = in[i] + (i >= off ? in[i - off] : 0);
            __syncthreads();
            int* tmp = in; in = out; out = tmp;
        }
        for (int i = t; i < N_; i += MT_) {
            if (ldvi(&g_mis[i])) { int p = in[i] - 1; g_colmap[i] = p; g_qlist[p] = i; }
            else g_colmap[i] = -1;
        }
        if (t == 0) g_M = in[N_ - 1];
    }
    gridbar(ph);

    // ---- fused zeroB: all 64K threads zero N*M floats ----
    {
        int M = ldvi(&g_M);
        size_t tot = (size_t)N_ * (size_t)M;
        for (size_t idx = tid; idx < tot; idx += (size_t)MB_ * MT_)
            g_B[idx] = 0.f;
    }
}

// ---------------- B = rw[:, MIS] (compact, stride M) ----------------
__global__ void k_buildB(const int* __restrict__ ei, const float* __restrict__ ea)
{
    int t = blockIdx.x * blockDim.x + threadIdx.x;
    if (t < E_) {
        int r = ei[t], c = ei[E_ + t];
        int cm = g_colmap[c];
        if (cm >= 0) atomicAdd(&g_B[(size_t)r * g_M + cm], 0.5f * ea[t] * g_invs[r]);
    } else {
        int i = t - E_;
        if (i < N_ && g_mis[i])
            atomicAdd(&g_B[(size_t)i * g_M + g_colmap[i]], g_dd[i]);
    }
}

// ---------------- c = rw @ B (sparse row), fused Gumbel-argmax + counts ----------------
__global__ void k_spmm(const float* __restrict__ u)
{
    int i = blockIdx.x;
    int t = threadIdx.x;
    int M = g_M;
    int nk = (M + 127) >> 7;   // <= 16
    float acc[16];
#pragma unroll
    for (int k = 0; k < 16; k++) acc[k] = 0.f;

    int beg = g_rpout[i], end = g_rpout[i + 1];
    for (int e = beg; e < end; e++) {
        int j = g_csrdst[e]; float wn = g_csrw[e];
        const float* Bj = g_B + (size_t)j * M;
        for (int k = 0; k < nk; k++) { int m = t + (k << 7); if (m < M) acc[k] += wn * Bj[m]; }
    }
    {
        float dd = g_dd[i];
        const float* Bi = g_B + (size_t)i * M;
        for (int k = 0; k < nk; k++) { int m = t + (k << 7); if (m < M) acc[k] += dd * Bi[m]; }
    }

    // argmax of log(c)+gumbel; row-normalization is a positive per-row scale -> skipped
    float best = -INFINITY; int bq = 0x7FFFFFFF;
    const float* ui = u + (size_t)i * N_;
    for (int k = 0; k < nk; k++) {
        int m = t + (k << 7);
        if (m < M) {
            float cv = acc[k];
            if (cv > 0.f) {
                int q = g_qlist[m];
                float uu = ui[q];
                float gum = -logf(-logf(uu + 1e-20f) + 1e-20f);
                float lg = logf(fmaxf(cv, 1e-30f)) + gum;
                if (lg > best || (lg == best && q < bq)) { best = lg; bq = q; }
            }
        }
    }
    __shared__ float sv[128]; __shared__ int sq[128];
    sv[t] = best; sq[t] = bq;
    __syncthreads();
    for (int o = 64; o > 0; o >>= 1) {
        if (t < o) {
            float v = sv[t + o]; int q = sq[t + o];
            if (v > sv[t] || (v == sv[t] && q < sq[t])) { sv[t] = v; sq[t] = q; }
        }
        __syncthreads();
    }
    if (t == 0) {
        int cl = (sq[0] == 0x7FFFFFFF) ? 0 : sq[0];
        g_cluster[i] = cl;
        atomicAdd(&g_counts[cl], 1);
    }
}

// ---------------- output zero-fill ----------------
__global__ void k_fillzero(float4* __restrict__ o, size_t tot4)
{
    for (size_t idx = blockIdx.x * (size_t)blockDim.x + threadIdx.x; idx < tot4;
         idx += (size_t)gridDim.x * blockDim.x)
        o[idx] = make_float4(0.f, 0.f, 0.f, 0.f);
}

// ---------------- fused post-pass: outputs + adj_c + x_pool ----------------
__global__ void k_post(const int* __restrict__ ei, const float* __restrict__ ea,
                       const float* __restrict__ x,
                       float* __restrict__ miso, float* __restrict__ chard,
                       float* __restrict__ pinv, float* __restrict__ adjc,
                       float* __restrict__ xp)
{
    int t = blockIdx.x * blockDim.x + threadIdx.x;
    if (t < N_) {
        int i = t;
        miso[i] = g_mis[i] ? 1.f : 0.f;
        int c = g_cluster[i];
        chard[(size_t)i * N_ + c] = 1.f;
        pinv[(size_t)c * N_ + i] = 1.f / (float)g_counts[c];
    } else if (t < N_ + E_) {
        int e = t - N_;
        int r = ei[e], c = ei[E_ + e];
        atomicAdd(&adjc[(size_t)g_cluster[r] * N_ + g_cluster[c]], ea[e]);
    } else {
        int idx = t - N_ - E_;
        if (idx < N_ * D_) {
            int i = idx / D_, d = idx % D_;
            int c = g_cluster[i];
            float invc = 1.f / (float)g_counts[c];
            atomicAdd(&xp[(size_t)c * D_ + d], x[idx] * invc);
        }
    }
}

// ---------------- launch ----------------
extern "C" void kernel_launch(void* const* d_in, const int* in_sizes, int n_in,
                              void* d_out, int out_size)
{
    const int*   ei   = (const int*)d_in[0];     // edge_index [2, E]
    const float* ea   = (const float*)d_in[1];   // edge_attr  [E]
    const float* x    = (const float*)d_in[2];   // x          [N, D]
    const int*   rank = (const int*)d_in[3];     // rank       [N]
    const float* u    = (const float*)d_in[4];   // u          [N, N]

    float* out   = (float*)d_out;
    size_t nn    = (size_t)N_ * N_;
    float* adjc  = out;
    float* chard = out + nn;
    float* pinv  = out + 2 * nn;
    float* miso  = out + 3 * nn;
    float* xpool = out + 3 * nn + N_;

    (void)in_sizes; (void)n_in;

    k_init    <<<(N_ + 255) / 256, 256>>>();
    k_edges1  <<<(E_ + 255) / 256, 256>>>(ei, ea);
    k_scan    <<<1, 1024>>>();
    k_edges2  <<<(E_ + 255) / 256, 256>>>(ei, ea);
    k_mis     <<<MB_, MT_>>>(rank);
    k_buildB  <<<(E_ + N_ + 255) / 256, 256>>>(ei, ea);

    size_t tot4 = (size_t)out_size >> 2;   // out_size divisible by 4 here
    k_fillzero<<<4096, 256>>>((float4*)out, tot4);

    k_spmm    <<<N_, 128>>>(u);

    int post_threads = N_ + E_ + N_ * D_;
    k_post    <<<(post_threads + 255) / 256, 256>>>(ei, ea, x, miso, chard, pinv, adjc, xpool);
}

// round 4
// speedup vs baseline: 2.1773x; 1.0337x over previous
#include <cuda_runtime.h>
#include <math.h>

#define N_ 2048
#define E_ 65536
#define D_ 512

#define MB_ 128                 // persistent blocks (<=148 SMs, all co-resident)
#define MT_ 512                 // threads/block
#define NT_ (MB_ * MT_)         // 65536 threads == E_

// ---------------- static device scratch (no allocations allowed) ----------------
__device__ int   g_degin[N_], g_degout[N_];
__device__ int   g_rpin[N_ + 1], g_rpout[N_ + 1];
__device__ int   g_curin[N_], g_curout[N_];
__device__ int   g_cscsrc[E_];        // CSC: senders grouped by receiver
__device__ int   g_csrdst[E_];        // CSR: dst grouped by src
__device__ float g_csrw[E_];          // prescaled 0.5*w/s_row
__device__ float g_s[N_], g_invs[N_], g_dd[N_], g_diag[N_];
__device__ int   g_bb[N_], g_mis[N_], g_mka[N_], g_mkb[N_], g_a[N_];
__device__ int   g_qlist[N_], g_colmap[N_];
__device__ int   g_M;
__device__ int   g_cluster[N_];
__device__ int   g_counts[N_];
__device__ int   g_cnt[2];
__device__ unsigned g_barcnt;
__device__ unsigned g_barrel;
__device__ float g_B[(size_t)N_ * N_]; // compact rw[:, MIS] (stride = M)

__device__ __forceinline__ int ldvi(const int* p) { return *(const volatile int*)p; }

// ---------------- per-replay reset + zero init ----------------
__global__ void k_init()
{
    int i = blockIdx.x * blockDim.x + threadIdx.x;
    if (i < N_) { g_degin[i] = 0; g_degout[i] = 0; g_s[i] = 0.f; g_diag[i] = 0.f; g_counts[i] = 0; }
    if (i == 0) { g_cnt[0] = 0; g_cnt[1] = 0; g_barcnt = 0u; g_barrel = 0u; }
}

// ---------------- grid barrier: ticket counter + read-only release word ----------------
__device__ __forceinline__ void gridbar(unsigned& ph)
{
    __syncthreads();
    if (threadIdx.x == 0) {
        __threadfence();
        unsigned t = atomicAdd(&g_barcnt, 1u);
        unsigned target = ph * (unsigned)MB_ + (unsigned)MB_;
        if (t + 1u == target) {
            *((volatile unsigned*)&g_barrel) = ph + 1u;     // last arrival releases
        } else {
            while (*((volatile unsigned*)&g_barrel) < ph + 1u) {}
        }
        __threadfence();
    }
    ph++;
    __syncthreads();
}

// ================= THE fused persistent kernel =================
__global__ void __launch_bounds__(MT_, 1)
k_all(const int* __restrict__ ei, const float* __restrict__ ea,
      const float* __restrict__ x, const int* __restrict__ rank,
      const float* __restrict__ u, float* __restrict__ out, int out_size)
{
    const int bid  = blockIdx.x;
    const int t    = threadIdx.x;
    const int tid  = bid * MT_ + t;
    const int lane = tid & 31;

    __shared__ int sA[N_], sB[N_];

    size_t nn = (size_t)N_ * N_;
    float* adjc  = out;
    float* chard = out + nn;
    float* pinv  = out + 2 * nn;
    float* miso  = out + 3 * nn;
    float* xpool = out + 3 * nn + N_;

    unsigned ph = 0;

    // ---- phase 1: edge pass 1 (degrees, row sums, diag). tid == edge id ----
    {
        int r = ei[tid], c = ei[E_ + tid];
        float w = ea[tid];
        atomicAdd(&g_degin[c], 1);
        atomicAdd(&g_degout[r], 1);
        atomicAdd(&g_s[r], w);
        if (r == c) atomicAdd(&g_diag[r], w);
    }
    gridbar(ph);

    // ---- phase 2: block0 scans rowptrs; other blocks zero output + invs/dd ----
    if (bid == 0) {
        for (int pass = 0; pass < 2; pass++) {
            const int* src = pass ? g_degout : g_degin;
            int* rp  = pass ? g_rpout : g_rpin;
            int* cur = pass ? g_curout : g_curin;
            for (int i = t; i < N_; i += MT_) sA[i] = src[i];
            __syncthreads();
            int* in = sA; int* outp = sB;
            for (int off = 1; off < N_; off <<= 1) {
                for (int i = t; i < N_; i += MT_)
                    outp[i] = in[i] + (i >= off ? in[i - off] : 0);
                __syncthreads();
                int* tmp = in; in = outp; outp = tmp;
            }
            for (int i = t; i < N_; i += MT_) { rp[i + 1] = in[i]; cur[i] = i ? in[i - 1] : 0; }
            if (t == 0) rp[0] = 0;
            __syncthreads();
        }
    } else {
        // invs/dd (blocks 1..4 cover N_)
        int i = (bid - 1) * MT_ + t;
        if (i < N_) {
            float s = g_s[i];
            float inv = s > 0.f ? 1.f / s : 1.f;
            g_invs[i] = inv;
            g_dd[i] = 0.5f * (1.f + g_diag[i] * inv);
        }
        // zero-fill the 54MB output (free: overlapped with block0's scan)
        float4* o4 = (float4*)out;
        size_t tot4 = (size_t)out_size >> 2;
        for (size_t idx = (size_t)(bid - 1) * MT_ + t; idx < tot4; idx += (size_t)(MB_ - 1) * MT_)
            o4[idx] = make_float4(0.f, 0.f, 0.f, 0.f);
    }
    gridbar(ph);

    // ---- phase 3: edge pass 2 (fill CSC/CSR, prescaled weights) ----
    {
        int r = ei[tid], c = ei[E_ + tid];
        int p = atomicAdd(&g_curin[c], 1);
        g_cscsrc[p] = r;
        int q = atomicAdd(&g_curout[r], 1);
        g_csrdst[q] = c;
        g_csrw[q] = 0.5f * ea[tid] * g_invs[r];
    }
    gridbar(ph);

    // ---- phase 4: k-hop MIS. 1 warp per node, reg-cached in-list ----
    const int n = tid >> 5;   // node == warp id (2048 warps)
    {
        for (int i = tid; i < N_; i += NT_) { g_a[i] = rank[i]; g_mis[i] = 0; }
    }
    const int beg = g_rpin[n];
    const int end = g_rpin[n + 1];
    const int deg = end - beg;
    const int src = (lane < deg) ? g_cscsrc[beg + lane] : -1;
    const int rk  = rank[n];
    gridbar(ph);

    for (int iter = 0; iter < N_; iter++) {
        // min-prop hop 1
        {
            int m = ldvi(&g_a[n]);
            if (src >= 0) m = min(m, ldvi(&g_a[src]));
            for (int e = beg + 32 + lane; e < end; e += 32) m = min(m, ldvi(&g_a[g_cscsrc[e]]));
            m = __reduce_min_sync(0xffffffffu, m);
            if (lane == 0) g_bb[n] = m;
        }
        gridbar(ph);
        // min-prop hop 2 + mis update
        {
            int m = ldvi(&g_bb[n]);
            if (src >= 0) m = min(m, ldvi(&g_bb[src]));
            for (int e = beg + 32 + lane; e < end; e += 32) m = min(m, ldvi(&g_bb[g_cscsrc[e]]));
            m = __reduce_min_sync(0xffffffffu, m);
            if (lane == 0) {
                int mi = g_mis[n] | (rk == m ? 1 : 0);
                g_mis[n] = mi;
                g_mka[n] = mi;
            }
        }
        gridbar(ph);
        // or-prop hop 1
        {
            int m = ldvi(&g_mka[n]);
            if (src >= 0) m = max(m, ldvi(&g_mka[src]));
            for (int e = beg + 32 + lane; e < end; e += 32) m = max(m, ldvi(&g_mka[g_cscsrc[e]]));
            m = __reduce_max_sync(0xffffffffu, m);
            if (lane == 0) g_mkb[n] = m;
        }
        gridbar(ph);
        // or-prop hop 2 + finalize
        if (tid == 0) g_cnt[(iter + 1) & 1] = 0;
        {
            int m = ldvi(&g_mkb[n]);
            if (src >= 0) m = max(m, ldvi(&g_mkb[src]));
            for (int e = beg + 32 + lane; e < end; e += 32) m = max(m, ldvi(&g_mkb[g_cscsrc[e]]));
            m = __reduce_max_sync(0xffffffffu, m);
            if (lane == 0) {
                int mask = m > 0;
                g_a[n] = mask ? N_ : rk;
                if (!mask) atomicAdd(&g_cnt[iter & 1], 1);
            }
        }
        gridbar(ph);
        if (ldvi(&g_cnt[iter & 1]) == 0) break;
    }

    // ---- compact (block 0) -> colmap/qlist/M ----
    if (bid == 0) {
        for (int i = t; i < N_; i += MT_) sA[i] = ldvi(&g_mis[i]);
        __syncthreads();
        int* in = sA; int* outp = sB;
        for (int off = 1; off < N_; off <<= 1) {
            for (int i = t; i < N_; i += MT_)
                outp[i] = in[i] + (i >= off ? in[i - off] : 0);
            __syncthreads();
            int* tmp = in; in = outp; outp = tmp;
        }
        for (int i = t; i < N_; i += MT_) {
            if (ldvi(&g_mis[i])) { int p = in[i] - 1; g_colmap[i] = p; g_qlist[p] = i; }
            else g_colmap[i] = -1;
        }
        if (t == 0) g_M = in[N_ - 1];
    }
    gridbar(ph);

    const int M = *((volatile int*)&g_M);

    // ---- zero B ----
    {
        size_t tot = (size_t)N_ * (size_t)M;
        for (size_t idx = tid; idx < tot; idx += NT_) g_B[idx] = 0.f;
    }
    gridbar(ph);

    // ---- build B = rw[:, MIS] ----
    {
        int r = ei[tid], c = ei[E_ + tid];
        int cm = g_colmap[c];
        if (cm >= 0) atomicAdd(&g_B[(size_t)r * M + cm], 0.5f * ea[tid] * g_invs[r]);
        if (tid < N_ && g_mis[tid])
            atomicAdd(&g_B[(size_t)tid * M + g_colmap[tid]], g_dd[tid]);
    }
    gridbar(ph);

    // ---- SpMM c = rw @ B (warp per row) + fused Gumbel argmax + counts ----
    {
        int i = n;   // row == warp id
        int rb = g_rpout[i], re = g_rpout[i + 1];
        float dd = g_dd[i];
        const float* ui = u + (size_t)i * N_;
        float best = -INFINITY; int bq = 0x7FFFFFFF;
        for (int m0 = 0; m0 < M; m0 += 32) {
            int m = m0 + lane;
            if (m < M) {
                float acc = dd * g_B[(size_t)i * M + m];
                for (int e = rb; e < re; e++)
                    acc += g_csrw[e] * g_B[(size_t)g_csrdst[e] * M + m];
                if (acc > 0.f) {
                    int q = g_qlist[m];
                    float uu = ui[q];
                    float gum = -logf(-logf(uu + 1e-20f) + 1e-20f);
                    float lg = logf(fmaxf(acc, 1e-30f)) + gum;
                    if (lg > best || (lg == best && q < bq)) { best = lg; bq = q; }
                }
            }
        }
        // warp argmax (ties -> smaller q, matching first-index argmax)
        for (int o = 16; o > 0; o >>= 1) {
            float v = __shfl_xor_sync(0xffffffffu, best, o);
            int   q = __shfl_xor_sync(0xffffffffu, bq, o);
            if (v > best || (v == best && q < bq)) { best = v; bq = q; }
        }
        if (lane == 0) {
            int cl = (bq == 0x7FFFFFFF) ? 0 : bq;
            g_cluster[i] = cl;
            atomicAdd(&g_counts[cl], 1);
        }
    }
    gridbar(ph);

    // ---- post: miso/chard/pinv + adj_c + x_pool ----
    if (tid < N_) {
        int i = tid;
        miso[i] = g_mis[i] ? 1.f : 0.f;
        int c = g_cluster[i];
        chard[(size_t)i * N_ + c] = 1.f;
        pinv[(size_t)c * N_ + i] = 1.f / (float)g_counts[c];
    }
    {
        int r = ei[tid], c = ei[E_ + tid];
        atomicAdd(&adjc[(size_t)g_cluster[r] * N_ + g_cluster[c]], ea[tid]);
    }
    for (int idx = tid; idx < N_ * D_; idx += NT_) {
        int i = idx >> 9, d = idx & (D_ - 1);      // D_ = 512
        int c = g_cluster[i];
        float invc = 1.f / (float)g_counts[c];
        atomicAdd(&xpool[(size_t)c * D_ + d], x[idx] * invc);
    }
}

// ---------------- launch ----------------
extern "C" void kernel_launch(void* const* d_in, const int* in_sizes, int n_in,
                              void* d_out, int out_size)
{
    const int*   ei   = (const int*)d_in[0];     // edge_index [2, E]
    const float* ea   = (const float*)d_in[1];   // edge_attr  [E]
    const float* x    = (const float*)d_in[2];   // x          [N, D]
    const int*   rank = (const int*)d_in[3];     // rank       [N]
    const float* u    = (const float*)d_in[4];   // u          [N, N]

    (void)in_sizes; (void)n_in;

    k_init<<<(N_ + 255) / 256, 256>>>();
    k_all <<<MB_, MT_>>>(ei, ea, x, rank, u, (float*)d_out, out_size);
}